// round 5
// baseline (speedup 1.0000x reference)
#include <cuda_runtime.h>

// ---------------- problem constants ----------------
#define NB      4096
#define NNOTES  48
#define NF      256
#define NU      256
#define NG      1024      // 4 * NU (i,f,g,o)
#define IN0     259       // NF + 3
#define MROWS   32        // batch rows per CTA
#define NTHR    512
#define KC      8         // K rows staged per chunk
#define XSTRIDE 260       // padded x row stride (multiple of 4)
#define RPT     8         // rows per thread

typedef unsigned long long u64;

// ---------------- device scratch (static, allocation-guard-safe) ----------------
__device__ __align__(16) float g_Wt_ih0[IN0 * NG];
__device__ __align__(16) float g_Wt_hh0[NU * NG];
__device__ __align__(16) float g_Wt_ih1[NU * NG];
__device__ __align__(16) float g_Wt_hh1[NU * NG];
__device__ __align__(16) float g_b0[NG];
__device__ __align__(16) float g_b1[NG];

// ---------------- helpers ----------------
__device__ __forceinline__ u64 pack2(float x) {
    u64 r;
    asm("mov.b64 %0, {%1, %1};" : "=l"(r) : "r"(__float_as_uint(x)));
    return r;
}
__device__ __forceinline__ u64 pack2f(float lo, float hi) {
    u64 r;
    asm("mov.b64 %0, {%1, %2};" : "=l"(r) : "r"(__float_as_uint(lo)), "r"(__float_as_uint(hi)));
    return r;
}
__device__ __forceinline__ void fma2(u64& acc, u64 a, u64 b) {
    // packed 2x fp32 FMA (sm_100+): acc = a*b + acc, per 32-bit lane
    asm("fma.rn.f32x2 %0, %1, %2, %0;" : "+l"(acc) : "l"(a), "l"(b));
}
__device__ __forceinline__ void unpack2(u64 v, float& lo, float& hi) {
    unsigned int a, b;
    asm("mov.b64 {%0, %1}, %2;" : "=r"(a), "=r"(b) : "l"(v));
    lo = __uint_as_float(a);
    hi = __uint_as_float(b);
}
__device__ __forceinline__ float sigf(float x) {
    return 1.0f / (1.0f + expf(-x));
}

// ---------------- prep: transpose weights, combine biases ----------------
__global__ void prep_kernel(const float* __restrict__ W_ih0, const float* __restrict__ W_hh0,
                            const float* __restrict__ b_ih0, const float* __restrict__ b_hh0,
                            const float* __restrict__ W_ih1, const float* __restrict__ W_hh1,
                            const float* __restrict__ b_ih1, const float* __restrict__ b_hh1) {
    int tid = blockIdx.x * blockDim.x + threadIdx.x;
    int stride = gridDim.x * blockDim.x;
    for (int i = tid; i < IN0 * NG; i += stride) {
        int k = i / NG, j = i - k * NG;
        g_Wt_ih0[i] = W_ih0[j * IN0 + k];
    }
    for (int i = tid; i < NU * NG; i += stride) {
        int k = i / NG, j = i - k * NG;
        g_Wt_hh0[i] = W_hh0[j * NU + k];
        g_Wt_ih1[i] = W_ih1[j * NU + k];
        g_Wt_hh1[i] = W_hh1[j * NU + k];
    }
    for (int i = tid; i < NG; i += stride) {
        g_b0[i] = b_ih0[i] + b_hh0[i];
        g_b1[i] = b_ih1[i] + b_hh1[i];
    }
}

// ---------------- GEMM accumulate (double-buffered W staging) ----------------
// Thread (rg, ug): rows rg*8..rg*8+7, per-gate column pair {2ug, 2ug+1}.
// acc[r][g] holds the packed pair for row r, gate g.
__device__ __forceinline__ void gemm_accum(
    u64 (&acc)[RPT][4],
    const float* Arow,             // this thread's first row (shared mem)
    int astride,
    const float* __restrict__ Wg,  // transposed weights [ktot][NG] in global
    int ktot,
    float* sh_w,                   // double buffer: 2 * KC * NG floats
    int ug, int tid)
{
    const int nch = (ktot + KC - 1) / KC;
    // prologue: stage chunk 0 into buffer 0
    {
        int kc0 = (ktot < KC) ? ktot : KC;
        int n4 = kc0 * (NG / 4);
        const float4* src = (const float4*)Wg;
        float4* dst = (float4*)sh_w;
#pragma unroll
        for (int j = 0; j < 4; j++) {
            int idx = tid + j * NTHR;
            if (idx < n4) dst[idx] = src[idx];
        }
    }
    __syncthreads();

    for (int ci = 0; ci < nch; ci++) {
        int k0 = ci * KC;
        int kc = ktot - k0; if (kc > KC) kc = KC;

        // prefetch next chunk into registers (LDG issued before compute)
        float4 ld0, ld1, ld2, ld3;
        int n4n = 0;
        if (ci + 1 < nch) {
            int kcn = ktot - (k0 + KC); if (kcn > KC) kcn = KC;
            n4n = kcn * (NG / 4);
            const float4* src = (const float4*)(Wg + (size_t)(k0 + KC) * NG);
            if (tid + 0 * NTHR < n4n) ld0 = src[tid + 0 * NTHR];
            if (tid + 1 * NTHR < n4n) ld1 = src[tid + 1 * NTHR];
            if (tid + 2 * NTHR < n4n) ld2 = src[tid + 2 * NTHR];
            if (tid + 3 * NTHR < n4n) ld3 = src[tid + 3 * NTHR];
        }

        // compute current chunk
        const float* wb = sh_w + (ci & 1) * (KC * NG) + 2 * ug;
        const float* ab = Arow + k0;
        if (kc == KC) {
#pragma unroll
            for (int kk = 0; kk < KC; kk++) {
                const float* wr = wb + kk * NG;
                u64 w0 = *(const u64*)(wr);
                u64 w1 = *(const u64*)(wr + 256);
                u64 w2 = *(const u64*)(wr + 512);
                u64 w3 = *(const u64*)(wr + 768);
#pragma unroll
                for (int r = 0; r < RPT; r++) {
                    u64 a = pack2(ab[r * astride + kk]);
                    fma2(acc[r][0], a, w0);
                    fma2(acc[r][1], a, w1);
                    fma2(acc[r][2], a, w2);
                    fma2(acc[r][3], a, w3);
                }
            }
        } else {
            for (int kk = 0; kk < kc; kk++) {
                const float* wr = wb + kk * NG;
                u64 w0 = *(const u64*)(wr);
                u64 w1 = *(const u64*)(wr + 256);
                u64 w2 = *(const u64*)(wr + 512);
                u64 w3 = *(const u64*)(wr + 768);
#pragma unroll
                for (int r = 0; r < RPT; r++) {
                    u64 a = pack2(ab[r * astride + kk]);
                    fma2(acc[r][0], a, w0);
                    fma2(acc[r][1], a, w1);
                    fma2(acc[r][2], a, w2);
                    fma2(acc[r][3], a, w3);
                }
            }
        }

        // commit prefetched chunk to the other buffer
        if (ci + 1 < nch) {
            float4* dst = (float4*)(sh_w + ((ci + 1) & 1) * (KC * NG));
            if (tid + 0 * NTHR < n4n) dst[tid + 0 * NTHR] = ld0;
            if (tid + 1 * NTHR < n4n) dst[tid + 1 * NTHR] = ld1;
            if (tid + 2 * NTHR < n4n) dst[tid + 2 * NTHR] = ld2;
            if (tid + 3 * NTHR < n4n) dst[tid + 3 * NTHR] = ld3;
        }
        __syncthreads();
    }
}

// ---------------- LSTM cell elementwise ----------------
// Thread owns rows row0..row0+7 and unit pair u0 = 2*ug (c entries exclusive).
__device__ __forceinline__ void cell_update(
    u64 (&acc)[RPT][4], float* shc, float* shh, int row0, int u0)
{
    float hn[RPT][2];
#pragma unroll
    for (int r = 0; r < RPT; r++) {
        int base = (row0 + r) * NU + u0;
        float iv0, iv1, fv0, fv1, gv0, gv1, ov0, ov1;
        unpack2(acc[r][0], iv0, iv1);
        unpack2(acc[r][1], fv0, fv1);
        unpack2(acc[r][2], gv0, gv1);
        unpack2(acc[r][3], ov0, ov1);
        float c0 = shc[base];
        float c1 = shc[base + 1];
        float cn0 = sigf(fv0) * c0 + sigf(iv0) * tanhf(gv0);
        float cn1 = sigf(fv1) * c1 + sigf(iv1) * tanhf(gv1);
        shc[base]     = cn0;   // thread-exclusive: no sync needed
        shc[base + 1] = cn1;
        hn[r][0] = sigf(ov0) * tanhf(cn0);
        hn[r][1] = sigf(ov1) * tanhf(cn1);
    }
    __syncthreads();   // all GEMM readers of old h are done
#pragma unroll
    for (int r = 0; r < RPT; r++) {
        int base = (row0 + r) * NU + u0;
        *(u64*)(shh + base) = pack2f(hn[r][0], hn[r][1]);   // STS.64
    }
    __syncthreads();
}

// ---------------- main persistent kernel ----------------
__global__ void __launch_bounds__(NTHR, 1)
noteaxis_kernel(const float* __restrict__ feats,
                const float* __restrict__ cond,
                const float* __restrict__ Wout,
                const float* __restrict__ bout,
                float* __restrict__ out)
{
    extern __shared__ float smem[];
    float* sh_w  = smem;                        // 2*KC*NG    = 16384 floats
    float* sh_x  = sh_w + 2 * KC * NG;          // 32*260     = 8320 floats
    float* sh_h0 = sh_x + MROWS * XSTRIDE;      // 8192
    float* sh_h1 = sh_h0 + MROWS * NU;          // 8192
    float* sh_c0 = sh_h1 + MROWS * NU;          // 8192
    float* sh_c1 = sh_c0 + MROWS * NU;          // 8192

    int tid = threadIdx.x;
    int rg = tid >> 7;         // 0..3 -> rows rg*8 .. rg*8+7
    int ug = tid & 127;        // per-gate column pair base = 2*ug
    int row0 = rg * RPT;
    int u0 = 2 * ug;
    size_t batch0 = (size_t)blockIdx.x * MROWS;

    for (int i = tid; i < MROWS * NU; i += NTHR) {
        sh_h0[i] = 0.f; sh_h1[i] = 0.f; sh_c0[i] = 0.f; sh_c1[i] = 0.f;
    }
    // (gemm_accum's prologue barrier orders the zero-init before first reads)

    for (int n = 0; n < NNOTES; n++) {
        // ---- load x tile: [32 rows][259] = features ++ shifted cond notes ----
        for (int i = tid; i < MROWS * (NF / 4); i += NTHR) {
            int r = i >> 6;
            int c = i & 63;
            float4 v = ((const float4*)(feats + ((batch0 + r) * NNOTES + n) * NF))[c];
            ((float4*)(sh_x + r * XSTRIDE))[c] = v;
        }
        if (tid < MROWS * 3) {
            int r = tid / 3, c = tid - r * 3;
            sh_x[r * XSTRIDE + NF + c] =
                (n == 0) ? 0.f : cond[((batch0 + r) * NNOTES + (n - 1)) * 3 + c];
        }
        // (gemm_accum's prologue barrier orders these writes before reads)

        u64 acc[RPT][4];

        // ---- layer 0 ----
#pragma unroll
        for (int g = 0; g < 4; g++) {
            u64 bv = *(const u64*)(g_b0 + g * 256 + u0);
#pragma unroll
            for (int r = 0; r < RPT; r++) acc[r][g] = bv;
        }
        gemm_accum(acc, sh_x + row0 * XSTRIDE, XSTRIDE, g_Wt_ih0, IN0, sh_w, ug, tid);
        gemm_accum(acc, sh_h0 + row0 * NU,     NU,      g_Wt_hh0, NU,  sh_w, ug, tid);
        cell_update(acc, sh_c0, sh_h0, row0, u0);

        // ---- layer 1 ----
#pragma unroll
        for (int g = 0; g < 4; g++) {
            u64 bv = *(const u64*)(g_b1 + g * 256 + u0);
#pragma unroll
            for (int r = 0; r < RPT; r++) acc[r][g] = bv;
        }
        gemm_accum(acc, sh_h0 + row0 * NU, NU, g_Wt_ih1, NU, sh_w, ug, tid);
        gemm_accum(acc, sh_h1 + row0 * NU, NU, g_Wt_hh1, NU, sh_w, ug, tid);
        cell_update(acc, sh_c1, sh_h1, row0, u0);

        // ---- output head: out[b,n,ch] = sigmoid?(h1 . Wout[ch] + bout[ch]) ----
        if (tid < MROWS * 3) {
            int r = tid / 3, ch = tid - r * 3;
            const float4* hv = (const float4*)(sh_h1 + r * NU);
            const float4* wv = (const float4*)(Wout + ch * NU);
            float s = bout[ch];
#pragma unroll 8
            for (int q = 0; q < NU / 4; q++) {
                float4 h4 = hv[q];
                float4 w4 = wv[q];
                s += h4.x * w4.x + h4.y * w4.y + h4.z * w4.z + h4.w * w4.w;
            }
            if (ch < 2) s = sigf(s);
            out[((batch0 + r) * NNOTES + n) * 3 + ch] = s;
        }
        // sh_h1 is not rewritten until next step's cell_update (after barriers),
        // and next step's x/w staging touches disjoint smem -> no extra barrier.
    }
}

// ---------------- launch ----------------
extern "C" void kernel_launch(void* const* d_in, const int* in_sizes, int n_in,
                              void* d_out, int out_size)
{
    const float* feats = (const float*)d_in[0];
    const float* cond  = (const float*)d_in[1];
    const float* W_ih0 = (const float*)d_in[2];
    const float* W_hh0 = (const float*)d_in[3];
    const float* b_ih0 = (const float*)d_in[4];
    const float* b_hh0 = (const float*)d_in[5];
    const float* W_ih1 = (const float*)d_in[6];
    const float* W_hh1 = (const float*)d_in[7];
    const float* b_ih1 = (const float*)d_in[8];
    const float* b_hh1 = (const float*)d_in[9];
    const float* W_out = (const float*)d_in[10];
    const float* b_out = (const float*)d_in[11];
    float* out = (float*)d_out;

    prep_kernel<<<264, 256>>>(W_ih0, W_hh0, b_ih0, b_hh0, W_ih1, W_hh1, b_ih1, b_hh1);

    int smem_bytes = (2 * KC * NG + MROWS * XSTRIDE + 4 * MROWS * NU) * (int)sizeof(float);
    cudaFuncSetAttribute(noteaxis_kernel,
                         cudaFuncAttributeMaxDynamicSharedMemorySize, smem_bytes);
    noteaxis_kernel<<<NB / MROWS, NTHR, smem_bytes>>>(feats, cond, W_out, b_out, out);
}

// round 6
// speedup vs baseline: 1.1469x; 1.1469x over previous
#include <cuda_runtime.h>

// ---------------- problem constants ----------------
#define NB      4096
#define NNOTES  48
#define NF      256
#define NU      256
#define NG      1024      // 4 * NU (i,f,g,o)
#define IN0     259       // NF + 3
#define MROWS   32        // batch rows per CTA
#define NTHR    1024
#define KC      8         // K rows staged per chunk
#define XSTRIDE 260       // padded x row stride (multiple of 4)
#define RPT     4         // rows per thread

typedef unsigned long long u64;

// ---------------- device scratch (static, allocation-guard-safe) ----------------
__device__ __align__(16) float g_Wt_ih0[IN0 * NG];
__device__ __align__(16) float g_Wt_hh0[NU * NG];
__device__ __align__(16) float g_Wt_ih1[NU * NG];
__device__ __align__(16) float g_Wt_hh1[NU * NG];
__device__ __align__(16) float g_b0[NG];
__device__ __align__(16) float g_b1[NG];

// ---------------- helpers ----------------
__device__ __forceinline__ u64 pack2(float x) {
    u64 r;
    asm("mov.b64 %0, {%1, %1};" : "=l"(r) : "r"(__float_as_uint(x)));
    return r;
}
__device__ __forceinline__ u64 pack2f(float lo, float hi) {
    u64 r;
    asm("mov.b64 %0, {%1, %2};" : "=l"(r) : "r"(__float_as_uint(lo)), "r"(__float_as_uint(hi)));
    return r;
}
__device__ __forceinline__ void fma2(u64& acc, u64 a, u64 b) {
    // packed 2x fp32 FMA (sm_100+): acc = a*b + acc, per 32-bit lane
    asm("fma.rn.f32x2 %0, %1, %2, %0;" : "+l"(acc) : "l"(a), "l"(b));
}
__device__ __forceinline__ void unpack2(u64 v, float& lo, float& hi) {
    unsigned int a, b;
    asm("mov.b64 {%0, %1}, %2;" : "=r"(a), "=r"(b) : "l"(v));
    lo = __uint_as_float(a);
    hi = __uint_as_float(b);
}
__device__ __forceinline__ float sigf(float x) {
    return 1.0f / (1.0f + expf(-x));
}

// ---------------- prep: transpose weights, combine biases ----------------
__global__ void prep_kernel(const float* __restrict__ W_ih0, const float* __restrict__ W_hh0,
                            const float* __restrict__ b_ih0, const float* __restrict__ b_hh0,
                            const float* __restrict__ W_ih1, const float* __restrict__ W_hh1,
                            const float* __restrict__ b_ih1, const float* __restrict__ b_hh1) {
    int tid = blockIdx.x * blockDim.x + threadIdx.x;
    int stride = gridDim.x * blockDim.x;
    for (int i = tid; i < IN0 * NG; i += stride) {
        int k = i / NG, j = i - k * NG;
        g_Wt_ih0[i] = W_ih0[j * IN0 + k];
    }
    for (int i = tid; i < NU * NG; i += stride) {
        int k = i / NG, j = i - k * NG;
        g_Wt_hh0[i] = W_hh0[j * NU + k];
        g_Wt_ih1[i] = W_ih1[j * NU + k];
        g_Wt_hh1[i] = W_hh1[j * NU + k];
    }
    for (int i = tid; i < NG; i += stride) {
        g_b0[i] = b_ih0[i] + b_hh0[i];
        g_b1[i] = b_ih1[i] + b_hh1[i];
    }
}

// ---------------- GEMM accumulate ----------------
// Thread (rg, ug): rows rg*4..rg*4+3, per-gate column pair {2ug, 2ug+1}.
// acc[r][g] holds the packed pair for row r, gate g.
__device__ __forceinline__ void gemm_accum(
    u64 (&acc)[RPT][4],
    const float* Arow,             // this thread's first row (shared mem)
    int astride,
    const float* __restrict__ Wg,  // transposed weights [ktot][NG] in global
    int ktot,
    float* sh_w, int ug, int tid)
{
    for (int k0 = 0; k0 < ktot; k0 += KC) {
        int kc = ktot - k0;
        if (kc > KC) kc = KC;
        __syncthreads();
        {
            int nf4 = kc * (NG / 4);
            const float4* src = (const float4*)(Wg + (size_t)k0 * NG);
            float4* dst = (float4*)sh_w;
#pragma unroll
            for (int j = 0; j < 2; j++) {
                int idx = tid + j * NTHR;
                if (idx < nf4) dst[idx] = src[idx];
            }
        }
        __syncthreads();
        const float* wb = sh_w + 2 * ug;
        const float* ab = Arow + k0;
        if (kc == KC) {
#pragma unroll
            for (int kk = 0; kk < KC; kk++) {
                const float* wr = wb + kk * NG;
                u64 w0 = *(const u64*)(wr);
                u64 w1 = *(const u64*)(wr + 256);
                u64 w2 = *(const u64*)(wr + 512);
                u64 w3 = *(const u64*)(wr + 768);
#pragma unroll
                for (int r = 0; r < RPT; r++) {
                    u64 a = pack2(ab[r * astride + kk]);   // warp-broadcast LDS
                    fma2(acc[r][0], a, w0);
                    fma2(acc[r][1], a, w1);
                    fma2(acc[r][2], a, w2);
                    fma2(acc[r][3], a, w3);
                }
            }
        } else {
            for (int kk = 0; kk < kc; kk++) {
                const float* wr = wb + kk * NG;
                u64 w0 = *(const u64*)(wr);
                u64 w1 = *(const u64*)(wr + 256);
                u64 w2 = *(const u64*)(wr + 512);
                u64 w3 = *(const u64*)(wr + 768);
#pragma unroll
                for (int r = 0; r < RPT; r++) {
                    u64 a = pack2(ab[r * astride + kk]);
                    fma2(acc[r][0], a, w0);
                    fma2(acc[r][1], a, w1);
                    fma2(acc[r][2], a, w2);
                    fma2(acc[r][3], a, w3);
                }
            }
        }
    }
}

// ---------------- LSTM cell elementwise ----------------
// Thread owns rows row0..row0+3 and unit pair u0 = 2*ug (c entries exclusive).
__device__ __forceinline__ void cell_update(
    u64 (&acc)[RPT][4], float* shc, float* shh, int row0, int u0)
{
    float hn[RPT][2];
#pragma unroll
    for (int r = 0; r < RPT; r++) {
        int base = (row0 + r) * NU + u0;
        float iv0, iv1, fv0, fv1, gv0, gv1, ov0, ov1;
        unpack2(acc[r][0], iv0, iv1);
        unpack2(acc[r][1], fv0, fv1);
        unpack2(acc[r][2], gv0, gv1);
        unpack2(acc[r][3], ov0, ov1);
        float c0 = shc[base];
        float c1 = shc[base + 1];
        float cn0 = sigf(fv0) * c0 + sigf(iv0) * tanhf(gv0);
        float cn1 = sigf(fv1) * c1 + sigf(iv1) * tanhf(gv1);
        shc[base]     = cn0;   // thread-exclusive: no sync needed
        shc[base + 1] = cn1;
        hn[r][0] = sigf(ov0) * tanhf(cn0);
        hn[r][1] = sigf(ov1) * tanhf(cn1);
    }
    __syncthreads();   // all GEMM readers of old h are done
#pragma unroll
    for (int r = 0; r < RPT; r++) {
        int base = (row0 + r) * NU + u0;
        *(u64*)(shh + base) = pack2f(hn[r][0], hn[r][1]);   // STS.64
    }
    __syncthreads();
}

// ---------------- main persistent kernel ----------------
__global__ void __launch_bounds__(NTHR, 1)
noteaxis_kernel(const float* __restrict__ feats,
                const float* __restrict__ cond,
                const float* __restrict__ Wout,
                const float* __restrict__ bout,
                float* __restrict__ out)
{
    extern __shared__ float smem[];
    float* sh_w  = smem;                        // KC*NG      = 8192 floats
    float* sh_x  = sh_w + KC * NG;              // 32*260     = 8320 floats
    float* sh_h0 = sh_x + MROWS * XSTRIDE;      // 8192
    float* sh_h1 = sh_h0 + MROWS * NU;          // 8192
    float* sh_c0 = sh_h1 + MROWS * NU;          // 8192
    float* sh_c1 = sh_c0 + MROWS * NU;          // 8192

    int tid = threadIdx.x;
    int rg = tid >> 7;         // 0..7 -> rows rg*4 .. rg*4+3
    int ug = tid & 127;        // per-gate column pair base = 2*ug
    int row0 = rg * RPT;
    int u0 = 2 * ug;
    size_t batch0 = (size_t)blockIdx.x * MROWS;

    for (int i = tid; i < MROWS * NU; i += NTHR) {
        sh_h0[i] = 0.f; sh_h1[i] = 0.f; sh_c0[i] = 0.f; sh_c1[i] = 0.f;
    }
    // (gemm_accum's leading barrier orders the zero-init before first reads)

    for (int n = 0; n < NNOTES; n++) {
        // ---- load x tile: [32 rows][259] = features ++ shifted cond notes ----
        for (int i = tid; i < MROWS * (NF / 4); i += NTHR) {
            int r = i >> 6;
            int c = i & 63;
            float4 v = ((const float4*)(feats + ((batch0 + r) * NNOTES + n) * NF))[c];
            ((float4*)(sh_x + r * XSTRIDE))[c] = v;
        }
        if (tid < MROWS * 3) {
            int r = tid / 3, c = tid - r * 3;
            sh_x[r * XSTRIDE + NF + c] =
                (n == 0) ? 0.f : cond[((batch0 + r) * NNOTES + (n - 1)) * 3 + c];
        }
        // (gemm_accum's leading barrier orders these writes before reads)

        u64 acc[RPT][4];

        // ---- layer 0 ----
#pragma unroll
        for (int g = 0; g < 4; g++) {
            u64 bv = *(const u64*)(g_b0 + g * 256 + u0);
#pragma unroll
            for (int r = 0; r < RPT; r++) acc[r][g] = bv;
        }
        gemm_accum(acc, sh_x + row0 * XSTRIDE, XSTRIDE, g_Wt_ih0, IN0, sh_w, ug, tid);
        gemm_accum(acc, sh_h0 + row0 * NU,     NU,      g_Wt_hh0, NU,  sh_w, ug, tid);
        cell_update(acc, sh_c0, sh_h0, row0, u0);

        // ---- layer 1 ----
#pragma unroll
        for (int g = 0; g < 4; g++) {
            u64 bv = *(const u64*)(g_b1 + g * 256 + u0);
#pragma unroll
            for (int r = 0; r < RPT; r++) acc[r][g] = bv;
        }
        gemm_accum(acc, sh_h0 + row0 * NU, NU, g_Wt_ih1, NU, sh_w, ug, tid);
        gemm_accum(acc, sh_h1 + row0 * NU, NU, g_Wt_hh1, NU, sh_w, ug, tid);
        cell_update(acc, sh_c1, sh_h1, row0, u0);

        // ---- output head: out[b,n,ch] = sigmoid?(h1 . Wout[ch] + bout[ch]) ----
        if (tid < MROWS * 3) {
            int r = tid / 3, ch = tid - r * 3;
            const float4* hv = (const float4*)(sh_h1 + r * NU);
            const float4* wv = (const float4*)(Wout + ch * NU);
            float s = bout[ch];
#pragma unroll 8
            for (int q = 0; q < NU / 4; q++) {
                float4 h4 = hv[q];
                float4 w4 = wv[q];
                s += h4.x * w4.x + h4.y * w4.y + h4.z * w4.z + h4.w * w4.w;
            }
            if (ch < 2) s = sigf(s);
            out[((batch0 + r) * NNOTES + n) * 3 + ch] = s;
        }
        // sh_h1 is not rewritten until next step's cell_update (after barriers),
        // and next step's x/w staging touches disjoint smem -> no extra barrier.
    }
}

// ---------------- launch ----------------
extern "C" void kernel_launch(void* const* d_in, const int* in_sizes, int n_in,
                              void* d_out, int out_size)
{
    const float* feats = (const float*)d_in[0];
    const float* cond  = (const float*)d_in[1];
    const float* W_ih0 = (const float*)d_in[2];
    const float* W_hh0 = (const float*)d_in[3];
    const float* b_ih0 = (const float*)d_in[4];
    const float* b_hh0 = (const float*)d_in[5];
    const float* W_ih1 = (const float*)d_in[6];
    const float* W_hh1 = (const float*)d_in[7];
    const float* b_ih1 = (const float*)d_in[8];
    const float* b_hh1 = (const float*)d_in[9];
    const float* W_out = (const float*)d_in[10];
    const float* b_out = (const float*)d_in[11];
    float* out = (float*)d_out;

    prep_kernel<<<264, 256>>>(W_ih0, W_hh0, b_ih0, b_hh0, W_ih1, W_hh1, b_ih1, b_hh1);

    int smem_bytes = (KC * NG + MROWS * XSTRIDE + 4 * MROWS * NU) * (int)sizeof(float);
    cudaFuncSetAttribute(noteaxis_kernel,
                         cudaFuncAttributeMaxDynamicSharedMemorySize, smem_bytes);
    noteaxis_kernel<<<NB / MROWS, NTHR, smem_bytes>>>(feats, cond, W_out, b_out, out);
}

// round 7
// speedup vs baseline: 1.1676x; 1.0181x over previous
#include <cuda_runtime.h>

// ---------------- problem constants ----------------
#define NB      4096
#define NNOTES  48
#define NF      256
#define NU      256
#define NG      1024      // 4 * NU (i,f,g,o)
#define K0TOT   516       // padded ih0 (260, last row zero) + hh0 (256)
#define K1TOT   512       // ih1 (256) + hh1 (256)
#define KC      4         // K rows per pipeline chunk
#define NSTAGE  3
#define MROWS   32        // batch rows per CTA
#define NTHR    1024
#define ASTR    36        // transposed-A row stride (32 rows + 4 pad, mult of 4)

typedef unsigned long long u64;

// ---------------- device scratch (static, allocation-guard-safe) ----------------
__device__ __align__(16) float g_W0[K0TOT * NG];   // [k][gatecol] layer 0 (ih pad ++ hh)
__device__ __align__(16) float g_W1[K1TOT * NG];   // [k][gatecol] layer 1 (ih ++ hh)
__device__ __align__(16) float g_b0[NG];
__device__ __align__(16) float g_b1[NG];

// ---------------- helpers ----------------
__device__ __forceinline__ u64 pack2(float x) {
    u64 r;
    asm("mov.b64 %0, {%1, %1};" : "=l"(r) : "r"(__float_as_uint(x)));
    return r;
}
__device__ __forceinline__ u64 pack2f(float lo, float hi) {
    u64 r;
    asm("mov.b64 %0, {%1, %2};" : "=l"(r) : "r"(__float_as_uint(lo)), "r"(__float_as_uint(hi)));
    return r;
}
__device__ __forceinline__ void fma2(u64& acc, u64 a, u64 b) {
    asm("fma.rn.f32x2 %0, %1, %2, %0;" : "+l"(acc) : "l"(a), "l"(b));
}
__device__ __forceinline__ void unpack2(u64 v, float& lo, float& hi) {
    unsigned int a, b;
    asm("mov.b64 {%0, %1}, %2;" : "=r"(a), "=r"(b) : "l"(v));
    lo = __uint_as_float(a);
    hi = __uint_as_float(b);
}
__device__ __forceinline__ float sigf(float x) {
    return 1.0f / (1.0f + expf(-x));
}
__device__ __forceinline__ void cp16(unsigned dst, const float* src) {
    asm volatile("cp.async.ca.shared.global [%0], [%1], 16;" :: "r"(dst), "l"(src) : "memory");
}
__device__ __forceinline__ void cp_commit() {
    asm volatile("cp.async.commit_group;" ::: "memory");
}
__device__ __forceinline__ void cp_wait1() {
    asm volatile("cp.async.wait_group 1;" ::: "memory");
}

// ---------------- prep: transpose + concatenate weights, combine biases ----------------
__global__ void prep_kernel(const float* __restrict__ W_ih0, const float* __restrict__ W_hh0,
                            const float* __restrict__ b_ih0, const float* __restrict__ b_hh0,
                            const float* __restrict__ W_ih1, const float* __restrict__ W_hh1,
                            const float* __restrict__ b_ih1, const float* __restrict__ b_hh1) {
    int tid = blockIdx.x * blockDim.x + threadIdx.x;
    int stride = gridDim.x * blockDim.x;
    for (int i = tid; i < K0TOT * NG; i += stride) {
        int k = i / NG, j = i - k * NG;
        float v;
        if (k < 259)      v = W_ih0[j * 259 + k];     // original IN0 = 259
        else if (k == 259) v = 0.f;                   // pad row (x[259] = 0 too)
        else              v = W_hh0[j * 256 + (k - 260)];
        g_W0[i] = v;
    }
    for (int i = tid; i < K1TOT * NG; i += stride) {
        int k = i / NG, j = i - k * NG;
        g_W1[i] = (k < 256) ? W_ih1[j * 256 + k] : W_hh1[j * 256 + (k - 256)];
    }
    for (int i = tid; i < NG; i += stride) {
        g_b0[i] = b_ih0[i] + b_hh0[i];
        g_b1[i] = b_ih1[i] + b_hh1[i];
    }
}

// ---------------- GEMM over one layer (concatenated ih++hh K range) ----------------
// Thread (rg, ug): rows rg*8..rg*8+7 (lanes = row pairs), unit ug, all 4 gates.
// A operands are TRANSPOSED in smem: A[k][row], row stride ASTR.
// W staged via 3-stage cp.async pipeline, KC k-rows per chunk.
__device__ __forceinline__ void gemm_layer(
    u64 (&acc)[4][4],
    const float* A0, const float* A1, int swChunk,   // A source switches at chunk swChunk
    const float* __restrict__ Wg, int nchunks,
    const float* sh_w, unsigned sw_u32, int tid, int rg8, int ug)
{
    // prologue: stage chunks 0 and 1
#pragma unroll
    for (int p = 0; p < 2; p++) {
        cp16(sw_u32 + (unsigned)(p * (KC * NG) + tid * 4) * 4u, Wg + p * (KC * NG) + tid * 4);
        cp_commit();
    }
    int stage = 0, stage2 = 2;   // stage of chunk ci, and of chunk ci+2
    for (int ci = 0; ci < nchunks; ci++) {
        cp_wait1();              // chunk ci (and older) arrived for THIS thread's copies
        __syncthreads();         // all threads' copies of chunk ci visible; stage2 free
        if (ci + 2 < nchunks) {
            cp16(sw_u32 + (unsigned)(stage2 * (KC * NG) + tid * 4) * 4u,
                 Wg + (size_t)(ci + 2) * (KC * NG) + tid * 4);
        }
        cp_commit();             // always commit (empty groups keep the count consistent)

        const float* wb = sh_w + stage * (KC * NG) + ug;
        const float* ab = (ci < swChunk ? A0 + ci * (KC * ASTR)
                                        : A1 + (ci - swChunk) * (KC * ASTR)) + rg8;
#pragma unroll
        for (int kk = 0; kk < KC; kk++) {
            float4 a03 = *(const float4*)(ab + kk * ASTR);       // rows rg8..rg8+3 (broadcast)
            float4 a47 = *(const float4*)(ab + kk * ASTR + 4);   // rows rg8+4..rg8+7
            u64 ap0 = pack2f(a03.x, a03.y);
            u64 ap1 = pack2f(a03.z, a03.w);
            u64 ap2 = pack2f(a47.x, a47.y);
            u64 ap3 = pack2f(a47.z, a47.w);
            const float* wr = wb + kk * NG;
            u64 wi = pack2(wr[0]);
            u64 wf = pack2(wr[256]);
            u64 wg = pack2(wr[512]);
            u64 wo = pack2(wr[768]);
            fma2(acc[0][0], ap0, wi); fma2(acc[1][0], ap1, wi);
            fma2(acc[2][0], ap2, wi); fma2(acc[3][0], ap3, wi);
            fma2(acc[0][1], ap0, wf); fma2(acc[1][1], ap1, wf);
            fma2(acc[2][1], ap2, wf); fma2(acc[3][1], ap3, wf);
            fma2(acc[0][2], ap0, wg); fma2(acc[1][2], ap1, wg);
            fma2(acc[2][2], ap2, wg); fma2(acc[3][2], ap3, wg);
            fma2(acc[0][3], ap0, wo); fma2(acc[1][3], ap1, wo);
            fma2(acc[2][3], ap2, wo); fma2(acc[3][3], ap3, wo);
        }
        stage = stage + 1;  if (stage == NSTAGE)  stage = 0;
        stage2 = stage2 + 1; if (stage2 == NSTAGE) stage2 = 0;
    }
}

// ---------------- LSTM cell elementwise ----------------
// Thread owns rows rg8..rg8+7 (as 4 lane-pairs) and unit ug; c is thread-exclusive.
// Writes new h into TRANSPOSED layout hT[unit][row].
__device__ __forceinline__ void cell_update(
    u64 (&acc)[4][4], float* c_state, float* hT, int rg8, int ug)
{
    float hn[8];
#pragma unroll
    for (int rp = 0; rp < 4; rp++) {
        float i0, i1, f0, f1, g0, g1, o0, o1;
        unpack2(acc[rp][0], i0, i1);
        unpack2(acc[rp][1], f0, f1);
        unpack2(acc[rp][2], g0, g1);
        unpack2(acc[rp][3], o0, o1);
        int r0 = rg8 + 2 * rp;
        float c0 = c_state[r0 * NU + ug];
        float c1 = c_state[(r0 + 1) * NU + ug];
        float cn0 = sigf(f0) * c0 + sigf(i0) * tanhf(g0);
        float cn1 = sigf(f1) * c1 + sigf(i1) * tanhf(g1);
        c_state[r0 * NU + ug]       = cn0;
        c_state[(r0 + 1) * NU + ug] = cn1;
        hn[2 * rp]     = sigf(o0) * tanhf(cn0);
        hn[2 * rp + 1] = sigf(o1) * tanhf(cn1);
    }
    __syncthreads();   // all GEMM readers of old hT are done
    float4* d = (float4*)(hT + ug * ASTR + rg8);
    d[0] = make_float4(hn[0], hn[1], hn[2], hn[3]);
    d[1] = make_float4(hn[4], hn[5], hn[6], hn[7]);
    __syncthreads();   // new hT visible (output head / next GEMM)
}

// ---------------- main persistent kernel ----------------
__global__ void __launch_bounds__(NTHR, 1)
noteaxis_kernel(const float* __restrict__ feats,
                const float* __restrict__ cond,
                const float* __restrict__ Wout,
                const float* __restrict__ bout,
                float* __restrict__ out)
{
    extern __shared__ float smem[];
    float* sh_w   = smem;                          // 3*4*1024 = 12288 floats
    float* sh_xT  = sh_w + NSTAGE * KC * NG;       // 260*36   = 9360
    float* sh_h0T = sh_xT + 260 * ASTR;            // 256*36   = 9216
    float* sh_h1T = sh_h0T + NU * ASTR;            // 9216
    float* sh_c0  = sh_h1T + NU * ASTR;            // 32*256   = 8192
    float* sh_c1  = sh_c0 + MROWS * NU;            // 8192
    unsigned sw_u32 = (unsigned)__cvta_generic_to_shared(sh_w);

    int tid = threadIdx.x;
    int rg  = tid >> 8;        // 0..3, warp-uniform
    int ug  = tid & 255;       // unit index
    int rg8 = rg * 8;
    size_t batch0 = (size_t)blockIdx.x * MROWS;

    for (int i = tid; i < NU * ASTR; i += NTHR) { sh_h0T[i] = 0.f; sh_h1T[i] = 0.f; }
    for (int i = tid; i < MROWS * NU; i += NTHR) { sh_c0[i] = 0.f; sh_c1[i] = 0.f; }
    // (first gemm iteration's __syncthreads orders the zero-init)

    for (int n = 0; n < NNOTES; n++) {
        // ---- stage x TRANSPOSED: xT[c][r]; coalesced global reads, scattered STS ----
        for (int idx = tid; idx < MROWS * NF; idx += NTHR) {
            int r = idx >> 8;          // NF = 256
            int c = idx & 255;
            sh_xT[c * ASTR + r] = feats[((batch0 + r) * NNOTES + n) * NF + c];
        }
        if (tid < MROWS * 4) {
            int r = tid >> 2, j = tid & 3;
            float v = 0.f;
            if (j < 3 && n > 0) v = cond[((batch0 + r) * NNOTES + (n - 1)) * 3 + j];
            sh_xT[(NF + j) * ASTR + r] = v;   // cols 256..258 = shifted cond, 259 = pad 0
        }
        // (gemm's first-iteration barrier orders these writes before reads)

        u64 acc[4][4];

        // ---- layer 0: gates = [x ++ h0_prev] @ W0^T + b0 ----
#pragma unroll
        for (int g = 0; g < 4; g++) {
            u64 bv = pack2(g_b0[g * 256 + ug]);
#pragma unroll
            for (int rp = 0; rp < 4; rp++) acc[rp][g] = bv;
        }
        gemm_layer(acc, sh_xT, sh_h0T, 260 / KC, g_W0, K0TOT / KC,
                   sh_w, sw_u32, tid, rg8, ug);
        cell_update(acc, sh_c0, sh_h0T, rg8, ug);

        // ---- layer 1: gates = [h0_new ++ h1_prev] @ W1^T + b1 ----
#pragma unroll
        for (int g = 0; g < 4; g++) {
            u64 bv = pack2(g_b1[g * 256 + ug]);
#pragma unroll
            for (int rp = 0; rp < 4; rp++) acc[rp][g] = bv;
        }
        gemm_layer(acc, sh_h0T, sh_h1T, 256 / KC, g_W1, K1TOT / KC,
                   sh_w, sw_u32, tid, rg8, ug);
        cell_update(acc, sh_c1, sh_h1T, rg8, ug);

        // ---- output head: out[b,n,ch] = sigmoid?(h1 . Wout[ch] + bout[ch]) ----
        if (tid < MROWS * 3) {
            int r = tid / 3, ch = tid - r * 3;
            const float* wv = Wout + ch * NU;
            float s = bout[ch];
#pragma unroll 8
            for (int u2 = 0; u2 < NU; u2++)
                s += sh_h1T[u2 * ASTR + r] * wv[u2];
            if (ch < 2) s = sigf(s);
            out[((batch0 + r) * NNOTES + n) * 3 + ch] = s;
        }
        // next staging (xT) is disjoint from h1T; gemm's first barrier gates reuse
    }
}

// ---------------- launch ----------------
extern "C" void kernel_launch(void* const* d_in, const int* in_sizes, int n_in,
                              void* d_out, int out_size)
{
    const float* feats = (const float*)d_in[0];
    const float* cond  = (const float*)d_in[1];
    const float* W_ih0 = (const float*)d_in[2];
    const float* W_hh0 = (const float*)d_in[3];
    const float* b_ih0 = (const float*)d_in[4];
    const float* b_hh0 = (const float*)d_in[5];
    const float* W_ih1 = (const float*)d_in[6];
    const float* W_hh1 = (const float*)d_in[7];
    const float* b_ih1 = (const float*)d_in[8];
    const float* b_hh1 = (const float*)d_in[9];
    const float* W_out = (const float*)d_in[10];
    const float* b_out = (const float*)d_in[11];
    float* out = (float*)d_out;

    prep_kernel<<<264, 256>>>(W_ih0, W_hh0, b_ih0, b_hh0, W_ih1, W_hh1, b_ih1, b_hh1);

    int smem_bytes = (NSTAGE * KC * NG + 260 * ASTR + 2 * NU * ASTR + 2 * MROWS * NU)
                     * (int)sizeof(float);   // 225,856 B
    cudaFuncSetAttribute(noteaxis_kernel,
                         cudaFuncAttributeMaxDynamicSharedMemorySize, smem_bytes);
    noteaxis_kernel<<<NB / MROWS, NTHR, smem_bytes>>>(feats, cond, W_out, b_out, out);
}

// round 8
// speedup vs baseline: 1.1693x; 1.0015x over previous
#include <cuda_runtime.h>

// ---------------- problem constants ----------------
#define NB      4096
#define NNOTES  48
#define NF      256
#define NU      256
#define NG      1024      // 4 * NU (i,f,g,o)
#define K0TOT   516       // padded ih0 (260, last row zero) + hh0 (256)
#define K1TOT   512       // ih1 (256) + hh1 (256)
#define KC      4         // K rows per pipeline chunk
#define NSTAGE  3
#define MROWS   32        // batch rows per CTA
#define NTHR    1024
#define ASTR    36        // transposed-A row stride (32 rows + 4 pad, mult of 4)

typedef unsigned long long u64;

// ---------------- device scratch (static, allocation-guard-safe) ----------------
__device__ __align__(16) float g_W0[K0TOT * NG];   // [k][gatecol] layer 0 (ih pad ++ hh)
__device__ __align__(16) float g_W1[K1TOT * NG];   // [k][gatecol] layer 1 (ih ++ hh)
__device__ __align__(16) float g_b0[NG];
__device__ __align__(16) float g_b1[NG];

// ---------------- helpers ----------------
__device__ __forceinline__ u64 pack2(float x) {
    u64 r;
    asm("mov.b64 %0, {%1, %1};" : "=l"(r) : "r"(__float_as_uint(x)));
    return r;
}
__device__ __forceinline__ u64 pack2f(float lo, float hi) {
    u64 r;
    asm("mov.b64 %0, {%1, %2};" : "=l"(r) : "r"(__float_as_uint(lo)), "r"(__float_as_uint(hi)));
    return r;
}
__device__ __forceinline__ void fma2(u64& acc, u64 a, u64 b) {
    asm("fma.rn.f32x2 %0, %1, %2, %0;" : "+l"(acc) : "l"(a), "l"(b));
}
__device__ __forceinline__ void unpack2(u64 v, float& lo, float& hi) {
    unsigned int a, b;
    asm("mov.b64 {%0, %1}, %2;" : "=r"(a), "=r"(b) : "l"(v));
    lo = __uint_as_float(a);
    hi = __uint_as_float(b);
}
__device__ __forceinline__ float sigf(float x) {
    return 1.0f / (1.0f + expf(-x));
}
__device__ __forceinline__ void cp16(unsigned dst, const float* src) {
    asm volatile("cp.async.ca.shared.global [%0], [%1], 16;" :: "r"(dst), "l"(src) : "memory");
}
__device__ __forceinline__ void cp_commit() {
    asm volatile("cp.async.commit_group;" ::: "memory");
}
__device__ __forceinline__ void cp_wait1() {
    asm volatile("cp.async.wait_group 1;" ::: "memory");
}

// ---------------- prep: transpose + concatenate weights, combine biases ----------------
__global__ void prep_kernel(const float* __restrict__ W_ih0, const float* __restrict__ W_hh0,
                            const float* __restrict__ b_ih0, const float* __restrict__ b_hh0,
                            const float* __restrict__ W_ih1, const float* __restrict__ W_hh1,
                            const float* __restrict__ b_ih1, const float* __restrict__ b_hh1) {
    int tid = blockIdx.x * blockDim.x + threadIdx.x;
    int stride = gridDim.x * blockDim.x;
    for (int i = tid; i < K0TOT * NG; i += stride) {
        int k = i / NG, j = i - k * NG;
        float v;
        if (k < 259)      v = W_ih0[j * 259 + k];     // original IN0 = 259
        else if (k == 259) v = 0.f;                   // pad row (x[259] = 0 too)
        else              v = W_hh0[j * 256 + (k - 260)];
        g_W0[i] = v;
    }
    for (int i = tid; i < K1TOT * NG; i += stride) {
        int k = i / NG, j = i - k * NG;
        g_W1[i] = (k < 256) ? W_ih1[j * 256 + k] : W_hh1[j * 256 + (k - 256)];
    }
    for (int i = tid; i < NG; i += stride) {
        g_b0[i] = b_ih0[i] + b_hh0[i];
        g_b1[i] = b_ih1[i] + b_hh1[i];
    }
}

// ---------------- GEMM over one layer (concatenated ih++hh K range) ----------------
// Thread (rg, ug): rows rg*8..rg*8+7 (lanes = row pairs), unit ug, all 4 gates.
// A operands are TRANSPOSED in smem: A[k][row], row stride ASTR.
// W staged via 3-stage cp.async pipeline, KC k-rows per chunk.
__device__ __forceinline__ void gemm_layer(
    u64 (&acc)[4][4],
    const float* A0, const float* A1, int swChunk,   // A source switches at chunk swChunk
    const float* __restrict__ Wg, int nchunks,
    const float* sh_w, unsigned sw_u32, int tid, int rg8, int ug)
{
    // prologue: stage chunks 0 and 1
#pragma unroll
    for (int p = 0; p < 2; p++) {
        cp16(sw_u32 + (unsigned)(p * (KC * NG) + tid * 4) * 4u, Wg + p * (KC * NG) + tid * 4);
        cp_commit();
    }
    int stage = 0, stage2 = 2;   // stage of chunk ci, and of chunk ci+2
    for (int ci = 0; ci < nchunks; ci++) {
        cp_wait1();              // chunk ci (and older) arrived for THIS thread's copies
        __syncthreads();         // all threads' copies of chunk ci visible; stage2 free
        if (ci + 2 < nchunks) {
            cp16(sw_u32 + (unsigned)(stage2 * (KC * NG) + tid * 4) * 4u,
                 Wg + (size_t)(ci + 2) * (KC * NG) + tid * 4);
        }
        cp_commit();             // always commit (empty groups keep the count consistent)

        const float* wb = sh_w + stage * (KC * NG) + ug;
        const float* ab = (ci < swChunk ? A0 + ci * (KC * ASTR)
                                        : A1 + (ci - swChunk) * (KC * ASTR)) + rg8;
#pragma unroll
        for (int kk = 0; kk < KC; kk++) {
            float4 a03 = *(const float4*)(ab + kk * ASTR);       // rows rg8..rg8+3 (broadcast)
            float4 a47 = *(const float4*)(ab + kk * ASTR + 4);   // rows rg8+4..rg8+7
            u64 ap0 = pack2f(a03.x, a03.y);
            u64 ap1 = pack2f(a03.z, a03.w);
            u64 ap2 = pack2f(a47.x, a47.y);
            u64 ap3 = pack2f(a47.z, a47.w);
            const float* wr = wb + kk * NG;
            u64 wi = pack2(wr[0]);
            u64 wf = pack2(wr[256]);
            u64 wg = pack2(wr[512]);
            u64 wo = pack2(wr[768]);
            fma2(acc[0][0], ap0, wi); fma2(acc[1][0], ap1, wi);
            fma2(acc[2][0], ap2, wi); fma2(acc[3][0], ap3, wi);
            fma2(acc[0][1], ap0, wf); fma2(acc[1][1], ap1, wf);
            fma2(acc[2][1], ap2, wf); fma2(acc[3][1], ap3, wf);
            fma2(acc[0][2], ap0, wg); fma2(acc[1][2], ap1, wg);
            fma2(acc[2][2], ap2, wg); fma2(acc[3][2], ap3, wg);
            fma2(acc[0][3], ap0, wo); fma2(acc[1][3], ap1, wo);
            fma2(acc[2][3], ap2, wo); fma2(acc[3][3], ap3, wo);
        }
        stage = stage + 1;  if (stage == NSTAGE)  stage = 0;
        stage2 = stage2 + 1; if (stage2 == NSTAGE) stage2 = 0;
    }
}

// ---------------- LSTM cell elementwise ----------------
// Thread owns rows rg8..rg8+7 (as 4 lane-pairs) and unit ug; c is thread-exclusive.
// Writes new h into TRANSPOSED layout hT[unit][row].
__device__ __forceinline__ void cell_update(
    u64 (&acc)[4][4], float* c_state, float* hT, int rg8, int ug)
{
    float hn[8];
#pragma unroll
    for (int rp = 0; rp < 4; rp++) {
        float i0, i1, f0, f1, g0, g1, o0, o1;
        unpack2(acc[rp][0], i0, i1);
        unpack2(acc[rp][1], f0, f1);
        unpack2(acc[rp][2], g0, g1);
        unpack2(acc[rp][3], o0, o1);
        int r0 = rg8 + 2 * rp;
        float c0 = c_state[r0 * NU + ug];
        float c1 = c_state[(r0 + 1) * NU + ug];
        float cn0 = sigf(f0) * c0 + sigf(i0) * tanhf(g0);
        float cn1 = sigf(f1) * c1 + sigf(i1) * tanhf(g1);
        c_state[r0 * NU + ug]       = cn0;
        c_state[(r0 + 1) * NU + ug] = cn1;
        hn[2 * rp]     = sigf(o0) * tanhf(cn0);
        hn[2 * rp + 1] = sigf(o1) * tanhf(cn1);
    }
    __syncthreads();   // all GEMM readers of old hT are done
    float4* d = (float4*)(hT + ug * ASTR + rg8);
    d[0] = make_float4(hn[0], hn[1], hn[2], hn[3]);
    d[1] = make_float4(hn[4], hn[5], hn[6], hn[7]);
    __syncthreads();   // new hT visible (output head / next GEMM)
}

// ---------------- main persistent kernel ----------------
__global__ void __launch_bounds__(NTHR, 1)
noteaxis_kernel(const float* __restrict__ feats,
                const float* __restrict__ cond,
                const float* __restrict__ Wout,
                const float* __restrict__ bout,
                float* __restrict__ out)
{
    extern __shared__ float smem[];
    float* sh_w   = smem;                          // 3*4*1024 = 12288 floats
    float* sh_xT  = sh_w + NSTAGE * KC * NG;       // 260*36   = 9360
    float* sh_h0T = sh_xT + 260 * ASTR;            // 256*36   = 9216
    float* sh_h1T = sh_h0T + NU * ASTR;            // 9216
    float* sh_c0  = sh_h1T + NU * ASTR;            // 32*256   = 8192
    float* sh_c1  = sh_c0 + MROWS * NU;            // 8192
    unsigned sw_u32 = (unsigned)__cvta_generic_to_shared(sh_w);

    int tid = threadIdx.x;
    int rg  = tid >> 8;        // 0..3, warp-uniform
    int ug  = tid & 255;       // unit index
    int rg8 = rg * 8;
    size_t batch0 = (size_t)blockIdx.x * MROWS;

    for (int i = tid; i < NU * ASTR; i += NTHR) { sh_h0T[i] = 0.f; sh_h1T[i] = 0.f; }
    for (int i = tid; i < MROWS * NU; i += NTHR) { sh_c0[i] = 0.f; sh_c1[i] = 0.f; }
    // (first gemm iteration's __syncthreads orders the zero-init)

    for (int n = 0; n < NNOTES; n++) {
        // ---- stage x TRANSPOSED: xT[c][r]; coalesced global reads, scattered STS ----
        for (int idx = tid; idx < MROWS * NF; idx += NTHR) {
            int r = idx >> 8;          // NF = 256
            int c = idx & 255;
            sh_xT[c * ASTR + r] = feats[((batch0 + r) * NNOTES + n) * NF + c];
        }
        if (tid < MROWS * 4) {
            int r = tid >> 2, j = tid & 3;
            float v = 0.f;
            if (j < 3 && n > 0) v = cond[((batch0 + r) * NNOTES + (n - 1)) * 3 + j];
            sh_xT[(NF + j) * ASTR + r] = v;   // cols 256..258 = shifted cond, 259 = pad 0
        }
        // (gemm's first-iteration barrier orders these writes before reads)

        u64 acc[4][4];

        // ---- layer 0: gates = [x ++ h0_prev] @ W0^T + b0 ----
#pragma unroll
        for (int g = 0; g < 4; g++) {
            u64 bv = pack2(g_b0[g * 256 + ug]);
#pragma unroll
            for (int rp = 0; rp < 4; rp++) acc[rp][g] = bv;
        }
        gemm_layer(acc, sh_xT, sh_h0T, 260 / KC, g_W0, K0TOT / KC,
                   sh_w, sw_u32, tid, rg8, ug);
        cell_update(acc, sh_c0, sh_h0T, rg8, ug);

        // ---- layer 1: gates = [h0_new ++ h1_prev] @ W1^T + b1 ----
#pragma unroll
        for (int g = 0; g < 4; g++) {
            u64 bv = pack2(g_b1[g * 256 + ug]);
#pragma unroll
            for (int rp = 0; rp < 4; rp++) acc[rp][g] = bv;
        }
        gemm_layer(acc, sh_h0T, sh_h1T, 256 / KC, g_W1, K1TOT / KC,
                   sh_w, sw_u32, tid, rg8, ug);
        cell_update(acc, sh_c1, sh_h1T, rg8, ug);

        // ---- output head: out[b,n,ch] = sigmoid?(h1 . Wout[ch] + bout[ch]) ----
        if (tid < MROWS * 3) {
            int r = tid / 3, ch = tid - r * 3;
            const float* wv = Wout + ch * NU;
            float s = bout[ch];
#pragma unroll 8
            for (int u2 = 0; u2 < NU; u2++)
                s += sh_h1T[u2 * ASTR + r] * wv[u2];
            if (ch < 2) s = sigf(s);
            out[((batch0 + r) * NNOTES + n) * 3 + ch] = s;
        }
        // next staging (xT) is disjoint from h1T; gemm's first barrier gates reuse
    }
}

// ---------------- launch ----------------
extern "C" void kernel_launch(void* const* d_in, const int* in_sizes, int n_in,
                              void* d_out, int out_size)
{
    const float* feats = (const float*)d_in[0];
    const float* cond  = (const float*)d_in[1];
    const float* W_ih0 = (const float*)d_in[2];
    const float* W_hh0 = (const float*)d_in[3];
    const float* b_ih0 = (const float*)d_in[4];
    const float* b_hh0 = (const float*)d_in[5];
    const float* W_ih1 = (const float*)d_in[6];
    const float* W_hh1 = (const float*)d_in[7];
    const float* b_ih1 = (const float*)d_in[8];
    const float* b_hh1 = (const float*)d_in[9];
    const float* W_out = (const float*)d_in[10];
    const float* b_out = (const float*)d_in[11];
    float* out = (float*)d_out;

    prep_kernel<<<264, 256>>>(W_ih0, W_hh0, b_ih0, b_hh0, W_ih1, W_hh1, b_ih1, b_hh1);

    int smem_bytes = (NSTAGE * KC * NG + 260 * ASTR + 2 * NU * ASTR + 2 * MROWS * NU)
                     * (int)sizeof(float);   // 225,856 B
    cudaFuncSetAttribute(noteaxis_kernel,
                         cudaFuncAttributeMaxDynamicSharedMemorySize, smem_bytes);
    noteaxis_kernel<<<NB / MROWS, NTHR, smem_bytes>>>(feats, cond, W_out, b_out, out);
}